// round 5
// baseline (speedup 1.0000x reference)
#include <cuda_runtime.h>
#include <cstdint>

// ---------------------------------------------------------------------------
// Problem constants
// ---------------------------------------------------------------------------
#define BB    128
#define CIN   96
#define HH    63
#define WW    63
#define COUT  256
#define HO    30
#define WO    30
#define HID   24
#define TEMPR 31.0f

#define KDIM  2400          // Cin * 25
#define PDIM  900           // Ho * Wo
#define PPAD  1024

// GEMM tiling: CTA 128(M=cout) x 256(N=p), 8 warps at 64x64
#define KSTEP   16
#define NKIT    (KDIM / KSTEP)   // 150
#define MT      128
#define NT      256
#define STAGES  5
#define ROWPAD  20                       // smem row stride (floats)
#define ATILE_F (MT * ROWPAD)            // 2560
#define BTILE_F (NT * ROWPAD)            // 5120
#define STAGE_F (ATILE_F + BTILE_F)      // 7680 floats
#define SMEM_B  (STAGES * STAGE_F * 4)   // 153600 bytes

#define PBLK  20            // output positions per im2col block

// ---------------------------------------------------------------------------
// Device scratch
// ---------------------------------------------------------------------------
__device__ float g_pooled[BB * CIN];
__device__ float g_att[BB * 2];
__device__ float g_w[(size_t)BB * COUT * KDIM];   // mixed weight, tf32-rounded
__device__ float g_x[(size_t)BB * PPAD * KDIM];   // im2col,     tf32-rounded

// ---------------------------------------------------------------------------
// Helpers
// ---------------------------------------------------------------------------
__device__ __forceinline__ float to_tf32(float v) {
    uint32_t o;
    asm("cvt.rna.tf32.f32 %0, %1;" : "=r"(o) : "f"(v));
    return __uint_as_float(o);
}

__device__ __forceinline__ uint32_t smem_u32(const void* p) {
    uint32_t a;
    asm("{ .reg .u64 t; cvta.to.shared.u64 t, %1; cvt.u32.u64 %0, t; }"
        : "=r"(a) : "l"(p));
    return a;
}

__device__ __forceinline__ void cp16(uint32_t dst, const float* src) {
    asm volatile("cp.async.cg.shared.global [%0], [%1], 16;"
                 :: "r"(dst), "l"(src) : "memory");
}
__device__ __forceinline__ void cp_commit() {
    asm volatile("cp.async.commit_group;" ::: "memory");
}
__device__ __forceinline__ void cp_wait3() {
    asm volatile("cp.async.wait_group 3;" ::: "memory");
}

__device__ __forceinline__ void mma_tf32(float* d, const uint32_t* a,
                                         const uint32_t* b) {
    asm volatile(
        "mma.sync.aligned.m16n8k8.row.col.f32.tf32.tf32.f32 "
        "{%0,%1,%2,%3}, {%4,%5,%6,%7}, {%8,%9}, {%0,%1,%2,%3};"
        : "+f"(d[0]), "+f"(d[1]), "+f"(d[2]), "+f"(d[3])
        : "r"(a[0]), "r"(a[1]), "r"(a[2]), "r"(a[3]), "r"(b[0]), "r"(b[1]));
}

// ---------------------------------------------------------------------------
// Kernel 1: global average pool
// ---------------------------------------------------------------------------
__global__ void pool_kernel(const float* __restrict__ x) {
    const int ci = blockIdx.x;
    const int b  = blockIdx.y;
    const float* p = x + ((size_t)(b * CIN + ci)) * (HH * WW);
    float s = 0.f;
    for (int i = threadIdx.x; i < HH * WW; i += blockDim.x) s += p[i];
    __shared__ float red[32];
    #pragma unroll
    for (int o = 16; o; o >>= 1) s += __shfl_down_sync(0xffffffffu, s, o);
    if ((threadIdx.x & 31) == 0) red[threadIdx.x >> 5] = s;
    __syncthreads();
    if (threadIdx.x < 32) {
        s = (threadIdx.x < (blockDim.x >> 5)) ? red[threadIdx.x] : 0.f;
        #pragma unroll
        for (int o = 16; o; o >>= 1) s += __shfl_down_sync(0xffffffffu, s, o);
        if (threadIdx.x == 0) g_pooled[b * CIN + ci] = s * (1.0f / (HH * WW));
    }
}

// ---------------------------------------------------------------------------
// Kernel 2: attention MLP + softmax
// ---------------------------------------------------------------------------
__global__ void att_kernel(const float* __restrict__ w1,
                           const float* __restrict__ w2) {
    const int b = threadIdx.x;
    float pooled[CIN];
    #pragma unroll 8
    for (int i = 0; i < CIN; i++) pooled[i] = g_pooled[b * CIN + i];
    float l0 = 0.f, l1 = 0.f;
    for (int j = 0; j < HID; j++) {
        float h = 0.f;
        #pragma unroll 8
        for (int i = 0; i < CIN; i++) h += pooled[i] * w1[j * CIN + i];
        h = fmaxf(h, 0.f);
        l0 += h * w2[0 * HID + j];
        l1 += h * w2[1 * HID + j];
    }
    l0 *= (1.0f / TEMPR);
    l1 *= (1.0f / TEMPR);
    const float m  = fmaxf(l0, l1);
    const float e0 = __expf(l0 - m);
    const float e1 = __expf(l1 - m);
    const float inv = 1.0f / (e0 + e1);
    g_att[b * 2 + 0] = e0 * inv;
    g_att[b * 2 + 1] = e1 * inv;
}

// ---------------------------------------------------------------------------
// Kernel 3: mixed weight -> tf32-rounded fp32
// ---------------------------------------------------------------------------
__global__ void wmix_kernel(const float* __restrict__ wc,
                            const float* __restrict__ we) {
    const int co = blockIdx.x;
    const int b  = blockIdx.y;
    const float a0 = g_att[2 * b], a1 = g_att[2 * b + 1];
    float* dst = g_w + ((size_t)b * COUT + co) * KDIM;
    const float* pc = wc + (size_t)co * KDIM;
    const float* pe = we + (size_t)co * KDIM;
    for (int k = threadIdx.x; k < KDIM; k += blockDim.x)
        dst[k] = to_tf32(a0 * pc[k] + a1 * pe[k]);
}

// ---------------------------------------------------------------------------
// Kernel 4: im2col via shared offset-LUT.  Block = (p-chunk of 20, b).
// LUT built once per block (2400 divides), then pure gather + float4 store.
// ---------------------------------------------------------------------------
__global__ void __launch_bounds__(256) im2col_kernel(const float* __restrict__ x) {
    const int b  = blockIdx.y;
    const int p0 = blockIdx.x * PBLK;
    __shared__ int4 lut4[KDIM / 4];     // 600 entries, 9.6 KB

    for (int k4 = threadIdx.x; k4 < KDIM / 4; k4 += 256) {
        const int k = k4 * 4;
        int o[4];
        #pragma unroll
        for (int j = 0; j < 4; j++) {
            const int kk = k + j;
            const int ci = kk / 25, t = kk - ci * 25;
            const int kh = t / 5, kw = t - kh * 5;
            o[j] = (ci * HH + kh) * WW + kw;
        }
        lut4[k4] = make_int4(o[0], o[1], o[2], o[3]);
    }
    __syncthreads();

    const float* xb0 = x + (size_t)b * CIN * HH * WW;
    #pragma unroll 1
    for (int i = 0; i < PBLK; i++) {
        const int p  = p0 + i;                       // always < 900 (45*20)
        const int oh = p / WO, ow = p - oh * WO;
        const float* xb = xb0 + (oh * 2) * WW + ow * 2;
        float* dst = g_x + ((size_t)b * PPAD + p) * KDIM;
        for (int k4 = threadIdx.x; k4 < KDIM / 4; k4 += 256) {
            const int4 o = lut4[k4];
            float4 v;
            v.x = to_tf32(xb[o.x]);
            v.y = to_tf32(xb[o.y]);
            v.z = to_tf32(xb[o.z]);
            v.w = to_tf32(xb[o.w]);
            *(float4*)(dst + k4 * 4) = v;
        }
    }
}

// ---------------------------------------------------------------------------
// Kernel 5: tf32 mma.sync GEMM.  CTA = (b, co_tile 128, p_tile 256).
// 8 warps (2x4), warp tile 64x64.  5-stage cp.async pipeline, KSTEP=16.
// ---------------------------------------------------------------------------
__global__ void __launch_bounds__(256, 1)
gemm_kernel(const float* __restrict__ cb, const float* __restrict__ eb,
            float* __restrict__ out)
{
    extern __shared__ float sm[];
    const int b   = blockIdx.y;
    const int ct  = blockIdx.x >> 2;          // 0..1  (co tile)
    const int pt  = blockIdx.x & 3;           // 0..3  (p tile)
    const int co0 = ct * MT;
    const int p0  = pt * NT;

    const int tid  = threadIdx.x;
    const int wid  = tid >> 5;
    const int lane = tid & 31;
    const int wm   = wid & 1;                 // warp M (2)
    const int wn   = wid >> 1;                // warp N (4)
    const int g    = lane >> 2;               // group 0..7
    const int t    = lane & 3;

    const float* gA = g_w + ((size_t)b * COUT + co0) * KDIM;
    const float* gB = g_x + ((size_t)b * PPAD + p0) * KDIM;

    const uint32_t smbase = smem_u32(sm);
    // staging: A = 512 float4-chunks (row=c>>2, seg=c&3); B = 1024 chunks
    const int ar0 = tid >> 2,           as0 = tid & 3;
    const int ar1 = (tid + 256) >> 2,   as1 = tid & 3;

    float acc[4][8][4];
    #pragma unroll
    for (int m = 0; m < 4; m++)
        #pragma unroll
        for (int n = 0; n < 8; n++)
            #pragma unroll
            for (int r = 0; r < 4; r++) acc[m][n][r] = 0.f;

    // ---- prologue: stage 0..2 ----
    #pragma unroll
    for (int s = 0; s < 3; s++) {
        const int k0 = s * KSTEP;
        const uint32_t abase = smbase + (uint32_t)(s * STAGE_F) * 4;
        const uint32_t bbase = abase + ATILE_F * 4;
        cp16(abase + (uint32_t)(ar0 * ROWPAD + as0 * 4) * 4, gA + (size_t)ar0 * KDIM + k0 + as0 * 4);
        cp16(abase + (uint32_t)(ar1 * ROWPAD + as1 * 4) * 4, gA + (size_t)ar1 * KDIM + k0 + as1 * 4);
        #pragma unroll
        for (int j = 0; j < 4; j++) {
            const int c = tid + 256 * j;
            const int br = c >> 2, bs = c & 3;
            cp16(bbase + (uint32_t)(br * ROWPAD + bs * 4) * 4, gB + (size_t)br * KDIM + k0 + bs * 4);
        }
        cp_commit();
    }

    // ---- main loop ----
    for (int it = 0; it < NKIT; it++) {
        if (it + 3 < NKIT) {
            const int s = (it + 3) % STAGES;
            const int k0 = (it + 3) * KSTEP;
            const uint32_t abase = smbase + (uint32_t)(s * STAGE_F) * 4;
            const uint32_t bbase = abase + ATILE_F * 4;
            cp16(abase + (uint32_t)(ar0 * ROWPAD + as0 * 4) * 4, gA + (size_t)ar0 * KDIM + k0 + as0 * 4);
            cp16(abase + (uint32_t)(ar1 * ROWPAD + as1 * 4) * 4, gA + (size_t)ar1 * KDIM + k0 + as1 * 4);
            #pragma unroll
            for (int j = 0; j < 4; j++) {
                const int c = tid + 256 * j;
                const int br = c >> 2, bs = c & 3;
                cp16(bbase + (uint32_t)(br * ROWPAD + bs * 4) * 4, gB + (size_t)br * KDIM + k0 + bs * 4);
            }
        }
        cp_commit();
        cp_wait3();
        __syncthreads();

        const float* As = sm + (it % STAGES) * STAGE_F;
        const float* Bs = As + ATILE_F;

        #pragma unroll
        for (int kk = 0; kk < 2; kk++) {
            const int c0 = kk * 8 + t;
            uint32_t afr[4][4];
            #pragma unroll
            for (int m = 0; m < 4; m++) {
                const int r = wm * 64 + m * 16 + g;
                afr[m][0] = __float_as_uint(As[r * ROWPAD + c0]);
                afr[m][1] = __float_as_uint(As[(r + 8) * ROWPAD + c0]);
                afr[m][2] = __float_as_uint(As[r * ROWPAD + c0 + 4]);
                afr[m][3] = __float_as_uint(As[(r + 8) * ROWPAD + c0 + 4]);
            }
            uint32_t bfr[8][2];
            #pragma unroll
            for (int n = 0; n < 8; n++) {
                const int col = wn * 64 + n * 8 + g;
                bfr[n][0] = __float_as_uint(Bs[col * ROWPAD + c0]);
                bfr[n][1] = __float_as_uint(Bs[col * ROWPAD + c0 + 4]);
            }
            #pragma unroll
            for (int m = 0; m < 4; m++)
                #pragma unroll
                for (int n = 0; n < 8; n++)
                    mma_tf32(acc[m][n], afr[m], bfr[n]);
        }
        __syncthreads();
    }

    // ---- epilogue ----
    const float a0 = g_att[2 * b], a1 = g_att[2 * b + 1];
    #pragma unroll
    for (int m = 0; m < 4; m++) {
        const int co_lo = co0 + wm * 64 + m * 16 + g;
        const int co_hi = co_lo + 8;
        const float bias_lo = a0 * cb[co_lo] + a1 * eb[co_lo];
        const float bias_hi = a0 * cb[co_hi] + a1 * eb[co_hi];
        float* op_lo = out + ((size_t)b * COUT + co_lo) * PDIM;
        float* op_hi = out + ((size_t)b * COUT + co_hi) * PDIM;
        #pragma unroll
        for (int n = 0; n < 8; n++) {
            const int p = p0 + wn * 64 + n * 8 + t * 2;
            if (p < PDIM) {
                float2 v0 = make_float2(acc[m][n][0] + bias_lo, acc[m][n][1] + bias_lo);
                float2 v1 = make_float2(acc[m][n][2] + bias_hi, acc[m][n][3] + bias_hi);
                *(float2*)(op_lo + p) = v0;
                *(float2*)(op_hi + p) = v1;
            }
        }
    }
}

// ---------------------------------------------------------------------------
// Host launch
// ---------------------------------------------------------------------------
extern "C" void kernel_launch(void* const* d_in, const int* in_sizes, int n_in,
                              void* d_out, int out_size) {
    (void)in_sizes; (void)n_in; (void)out_size;
    const float* x  = (const float*)d_in[0];
    const float* wc = (const float*)d_in[1];
    const float* cb = (const float*)d_in[2];
    const float* we = (const float*)d_in[3];
    const float* eb = (const float*)d_in[4];
    const float* w1 = (const float*)d_in[5];
    const float* w2 = (const float*)d_in[6];
    float* out = (float*)d_out;

    pool_kernel<<<dim3(CIN, BB), 256>>>(x);
    att_kernel<<<1, BB>>>(w1, w2);
    wmix_kernel<<<dim3(COUT, BB), 256>>>(wc, we);
    im2col_kernel<<<dim3(PDIM / PBLK, BB), 256>>>(x);

    static bool attr_set = false;
    if (!attr_set) {
        cudaFuncSetAttribute(gemm_kernel,
                             cudaFuncAttributeMaxDynamicSharedMemorySize, SMEM_B);
        attr_set = true;
    }
    gemm_kernel<<<dim3(8, BB), 256, SMEM_B>>>(cb, eb, out);
}

// round 7
// speedup vs baseline: 1.7096x; 1.7096x over previous
#include <cuda_runtime.h>
#include <cuda_fp16.h>
#include <cstdint>

// ---------------------------------------------------------------------------
// Problem constants
// ---------------------------------------------------------------------------
#define BB    128
#define CIN   96
#define HH    63
#define WW    63
#define COUT  256
#define HO    30
#define WO    30
#define HID   24
#define TEMPR 31.0f

#define KDIM  2400          // Cin * 25
#define PDIM  900           // Ho * Wo
#define PPAD  1024

// GEMM tiling: CTA 128(M=cout) x 256(N=p), 8 warps at 64x64, fp16 inputs
#define KSTEP   32                      // fp16 elems per K-iter
#define NKIT    (KDIM / KSTEP)          // 75
#define MT      128
#define NT      256
#define STAGES  5
#define AROWU   20                      // row stride in u32 (16 data + 4 pad) = 80B
#define ATILE_U (MT * AROWU)            // 2560
#define BTILE_U (NT * AROWU)            // 5120
#define STAGE_U (ATILE_U + BTILE_U)     // 7680
#define SMEM_B  (STAGES * STAGE_U * 4)  // 153600 bytes

// im2col: block = (oh, half, b); stages 48ci x 5rows x 63cols slab
#define CIH     48                      // channels per half
#define SLABF   (CIH * 5 * 64)          // 15360 floats
#define IMSMEM  (SLABF * 4 + 1200 * 4)  // slab + soff LUT = 66240 B

// ---------------------------------------------------------------------------
// Device scratch (force wide alignment: these are viewed as u32 / 16B chunks)
// ---------------------------------------------------------------------------
__device__ float g_pooled[BB * CIN];
__device__ float g_att[BB * 2];
__device__ __align__(256) __half g_wh[(size_t)BB * COUT * KDIM];
__device__ __align__(256) __half g_xh[(size_t)BB * PPAD * KDIM];
__device__ int g_soff[1200];

// ---------------------------------------------------------------------------
// Helpers
// ---------------------------------------------------------------------------
__device__ __forceinline__ uint32_t smem_u32(const void* p) {
    uint32_t a;
    asm("{ .reg .u64 t; cvta.to.shared.u64 t, %1; cvt.u32.u64 %0, t; }"
        : "=r"(a) : "l"(p));
    return a;
}
__device__ __forceinline__ void cp16(uint32_t dst, const void* src) {
    asm volatile("cp.async.cg.shared.global [%0], [%1], 16;"
                 :: "r"(dst), "l"(src) : "memory");
}
__device__ __forceinline__ void cp_commit() {
    asm volatile("cp.async.commit_group;" ::: "memory");
}
__device__ __forceinline__ void cp_wait3() {
    asm volatile("cp.async.wait_group 3;" ::: "memory");
}
__device__ __forceinline__ void mma_f16(float* d, const uint32_t* a,
                                        const uint32_t* b) {
    asm volatile(
        "mma.sync.aligned.m16n8k16.row.col.f32.f16.f16.f32 "
        "{%0,%1,%2,%3}, {%4,%5,%6,%7}, {%8,%9}, {%0,%1,%2,%3};"
        : "+f"(d[0]), "+f"(d[1]), "+f"(d[2]), "+f"(d[3])
        : "r"(a[0]), "r"(a[1]), "r"(a[2]), "r"(a[3]), "r"(b[0]), "r"(b[1]));
}
__device__ __forceinline__ uint32_t pack_h2(float v0, float v1) {
    __half2 h;
    h.x = __float2half_rn(v0);
    h.y = __float2half_rn(v1);
    return *(uint32_t*)&h;
}

// ---------------------------------------------------------------------------
// Kernel 1: global average pool
// ---------------------------------------------------------------------------
__global__ void pool_kernel(const float* __restrict__ x) {
    const int ci = blockIdx.x;
    const int b  = blockIdx.y;
    const float* p = x + ((size_t)(b * CIN + ci)) * (HH * WW);
    float s = 0.f;
    for (int i = threadIdx.x; i < HH * WW; i += blockDim.x) s += p[i];
    __shared__ float red[32];
    #pragma unroll
    for (int o = 16; o; o >>= 1) s += __shfl_down_sync(0xffffffffu, s, o);
    if ((threadIdx.x & 31) == 0) red[threadIdx.x >> 5] = s;
    __syncthreads();
    if (threadIdx.x < 32) {
        s = (threadIdx.x < (blockDim.x >> 5)) ? red[threadIdx.x] : 0.f;
        #pragma unroll
        for (int o = 16; o; o >>= 1) s += __shfl_down_sync(0xffffffffu, s, o);
        if (threadIdx.x == 0) g_pooled[b * CIN + ci] = s * (1.0f / (HH * WW));
    }
}

// ---------------------------------------------------------------------------
// Kernel 2: attention MLP + softmax; also builds the im2col smem-offset LUT
// ---------------------------------------------------------------------------
__global__ void att_kernel(const float* __restrict__ w1,
                           const float* __restrict__ w2) {
    const int b = threadIdx.x;
    for (int j = threadIdx.x; j < 1200; j += blockDim.x) {
        const int cl = j / 25, t = j - cl * 25;
        const int kh = t / 5, kw = t - kh * 5;
        g_soff[j] = (cl * 5 + kh) * 64 + kw;
    }
    if (b >= BB) return;
    float pooled[CIN];
    #pragma unroll 8
    for (int i = 0; i < CIN; i++) pooled[i] = g_pooled[b * CIN + i];
    float l0 = 0.f, l1 = 0.f;
    for (int j = 0; j < HID; j++) {
        float h = 0.f;
        #pragma unroll 8
        for (int i = 0; i < CIN; i++) h += pooled[i] * w1[j * CIN + i];
        h = fmaxf(h, 0.f);
        l0 += h * w2[0 * HID + j];
        l1 += h * w2[1 * HID + j];
    }
    l0 *= (1.0f / TEMPR);
    l1 *= (1.0f / TEMPR);
    const float m  = fmaxf(l0, l1);
    const float e0 = __expf(l0 - m);
    const float e1 = __expf(l1 - m);
    const float inv = 1.0f / (e0 + e1);
    g_att[b * 2 + 0] = e0 * inv;
    g_att[b * 2 + 1] = e1 * inv;
}

// ---------------------------------------------------------------------------
// Kernel 3: mixed weight -> fp16
// ---------------------------------------------------------------------------
__global__ void wmix_kernel(const float* __restrict__ wc,
                            const float* __restrict__ we) {
    const int co = blockIdx.x;
    const int b  = blockIdx.y;
    const float a0 = g_att[2 * b], a1 = g_att[2 * b + 1];
    uint32_t* dst = (uint32_t*)(g_wh + ((size_t)b * COUT + co) * KDIM);
    const float* pc = wc + (size_t)co * KDIM;
    const float* pe = we + (size_t)co * KDIM;
    for (int k2 = threadIdx.x; k2 < KDIM / 2; k2 += blockDim.x) {
        const int k = k2 * 2;
        dst[k2] = pack_h2(a0 * pc[k] + a1 * pe[k],
                          a0 * pc[k + 1] + a1 * pe[k + 1]);
    }
}

// ---------------------------------------------------------------------------
// Kernel 4: im2col -> fp16 with smem slab staging.
// Block = (oh, half, b).  Stage 48ci x 5 rows x 63 cols, then write
// 30 ow x 600 uint32 (1200 fp16) coalesced.
// ---------------------------------------------------------------------------
__global__ void __launch_bounds__(256) im2col_kernel(const float* __restrict__ x) {
    extern __shared__ float slab[];                // [48*5*64]
    int* soff = (int*)(slab + SLABF);              // [1200]

    const int oh   = blockIdx.x;
    const int half = blockIdx.y;
    const int b    = blockIdx.z;
    const int ci0  = half * CIH;
    const int tid  = threadIdx.x;
    const int wid  = tid >> 5, lane = tid & 31;

    for (int j = tid; j < 1200; j += 256) soff[j] = g_soff[j];

    const float* xb = x + ((size_t)b * CIN + ci0) * (HH * WW) + (size_t)(oh * 2) * WW;
    for (int row = wid; row < CIH * 5; row += 8) {
        const int cl = row / 5, kh = row - cl * 5;
        const float* src = xb + (size_t)cl * (HH * WW) + kh * WW;
        float* dstr = slab + row * 64;
        if (lane < 63) dstr[lane] = src[lane];
        if (lane < 31) dstr[lane + 32] = src[lane + 32];
    }
    __syncthreads();

    uint32_t* dst0 = (uint32_t*)(g_xh + ((size_t)b * PPAD + oh * WO) * KDIM
                                 + (size_t)ci0 * 25);
    const int rowstep = KDIM / 2;                  // uint32 per p row
    for (int idx = tid; idx < WO * 600; idx += 256) {
        const int ow = idx / 600;
        const int j2 = idx - ow * 600;
        const int j  = j2 * 2;
        const int base = ow * 2;
        const float v0 = slab[soff[j] + base];
        const float v1 = slab[soff[j + 1] + base];
        dst0[(size_t)ow * rowstep + j2] = pack_h2(v0, v1);
    }
}

// ---------------------------------------------------------------------------
// Kernel 5: fp16 mma.sync GEMM (m16n8k16).  CTA = (b, co 128, p 256).
// 8 warps (2x4), warp tile 64x64.  5-stage cp.async, KSTEP=32.
// ---------------------------------------------------------------------------
__global__ void __launch_bounds__(256, 1)
gemm_kernel(const float* __restrict__ cb, const float* __restrict__ eb,
            float* __restrict__ out)
{
    extern __shared__ uint32_t sm[];
    const int b   = blockIdx.y;
    const int ct  = blockIdx.x >> 2;
    const int pt  = blockIdx.x & 3;
    const int co0 = ct * MT;
    const int p0  = pt * NT;

    const int tid  = threadIdx.x;
    const int wid  = tid >> 5;
    const int lane = tid & 31;
    const int wm   = wid & 1;
    const int wn   = wid >> 1;
    const int g    = lane >> 2;
    const int t    = lane & 3;

    const __half* gA = g_wh + ((size_t)b * COUT + co0) * KDIM;
    const __half* gB = g_xh + ((size_t)b * PPAD + p0) * KDIM;

    const uint32_t smbase = smem_u32(sm);
    const int ar0 = tid >> 2, as0 = tid & 3;           // A: 512 16B chunks
    const int ar1 = (tid + 256) >> 2;

    float acc[4][8][4];
    #pragma unroll
    for (int m = 0; m < 4; m++)
        #pragma unroll
        for (int n = 0; n < 8; n++)
            #pragma unroll
            for (int r = 0; r < 4; r++) acc[m][n][r] = 0.f;

    // ---- prologue ----
    #pragma unroll
    for (int s = 0; s < 3; s++) {
        const int k0 = s * KSTEP;
        const uint32_t ab = smbase + (uint32_t)(s * STAGE_U) * 4;
        const uint32_t bb = ab + ATILE_U * 4;
        cp16(ab + (uint32_t)(ar0 * AROWU + as0 * 4) * 4, gA + (size_t)ar0 * KDIM + k0 + as0 * 8);
        cp16(ab + (uint32_t)(ar1 * AROWU + as0 * 4) * 4, gA + (size_t)ar1 * KDIM + k0 + as0 * 8);
        #pragma unroll
        for (int j = 0; j < 4; j++) {
            const int c = tid + 256 * j;
            const int br = c >> 2, bs = c & 3;
            cp16(bb + (uint32_t)(br * AROWU + bs * 4) * 4, gB + (size_t)br * KDIM + k0 + bs * 8);
        }
        cp_commit();
    }

    // ---- main loop ----
    for (int it = 0; it < NKIT; it++) {
        if (it + 3 < NKIT) {
            const int s = (it + 3) % STAGES;
            const int k0 = (it + 3) * KSTEP;
            const uint32_t ab = smbase + (uint32_t)(s * STAGE_U) * 4;
            const uint32_t bb = ab + ATILE_U * 4;
            cp16(ab + (uint32_t)(ar0 * AROWU + as0 * 4) * 4, gA + (size_t)ar0 * KDIM + k0 + as0 * 8);
            cp16(ab + (uint32_t)(ar1 * AROWU + as0 * 4) * 4, gA + (size_t)ar1 * KDIM + k0 + as0 * 8);
            #pragma unroll
            for (int j = 0; j < 4; j++) {
                const int c = tid + 256 * j;
                const int br = c >> 2, bs = c & 3;
                cp16(bb + (uint32_t)(br * AROWU + bs * 4) * 4, gB + (size_t)br * KDIM + k0 + bs * 8);
            }
        }
        cp_commit();
        cp_wait3();
        __syncthreads();

        const uint32_t* As = sm + (it % STAGES) * STAGE_U;
        const uint32_t* Bs = As + ATILE_U;

        #pragma unroll
        for (int kk = 0; kk < 2; kk++) {
            const int c0 = kk * 8 + t;
            uint32_t afr[4][4];
            #pragma unroll
            for (int m = 0; m < 4; m++) {
                const int r = wm * 64 + m * 16 + g;
                afr[m][0] = As[r * AROWU + c0];
                afr[m][1] = As[(r + 8) * AROWU + c0];
                afr[m][2] = As[r * AROWU + c0 + 4];
                afr[m][3] = As[(r + 8) * AROWU + c0 + 4];
            }
            uint32_t bfr[8][2];
            #pragma unroll
            for (int n = 0; n < 8; n++) {
                const int col = wn * 64 + n * 8 + g;
                bfr[n][0] = Bs[col * AROWU + c0];
                bfr[n][1] = Bs[col * AROWU + c0 + 4];
            }
            #pragma unroll
            for (int m = 0; m < 4; m++)
                #pragma unroll
                for (int n = 0; n < 8; n++)
                    mma_f16(acc[m][n], afr[m], bfr[n]);
        }
        __syncthreads();
    }

    // ---- epilogue ----
    const float a0 = g_att[2 * b], a1 = g_att[2 * b + 1];
    #pragma unroll
    for (int m = 0; m < 4; m++) {
        const int co_lo = co0 + wm * 64 + m * 16 + g;
        const int co_hi = co_lo + 8;
        const float bias_lo = a0 * cb[co_lo] + a1 * eb[co_lo];
        const float bias_hi = a0 * cb[co_hi] + a1 * eb[co_hi];
        float* op_lo = out + ((size_t)b * COUT + co_lo) * PDIM;
        float* op_hi = out + ((size_t)b * COUT + co_hi) * PDIM;
        #pragma unroll
        for (int n = 0; n < 8; n++) {
            const int p = p0 + wn * 64 + n * 8 + t * 2;
            if (p < PDIM) {
                float2 v0 = make_float2(acc[m][n][0] + bias_lo, acc[m][n][1] + bias_lo);
                float2 v1 = make_float2(acc[m][n][2] + bias_hi, acc[m][n][3] + bias_hi);
                *(float2*)(op_lo + p) = v0;
                *(float2*)(op_hi + p) = v1;
            }
        }
    }
}

// ---------------------------------------------------------------------------
// Host launch
// ---------------------------------------------------------------------------
extern "C" void kernel_launch(void* const* d_in, const int* in_sizes, int n_in,
                              void* d_out, int out_size) {
    (void)in_sizes; (void)n_in; (void)out_size;
    const float* x  = (const float*)d_in[0];
    const float* wc = (const float*)d_in[1];
    const float* cb = (const float*)d_in[2];
    const float* we = (const float*)d_in[3];
    const float* eb = (const float*)d_in[4];
    const float* w1 = (const float*)d_in[5];
    const float* w2 = (const float*)d_in[6];
    float* out = (float*)d_out;

    static bool attr_set = false;
    if (!attr_set) {
        cudaFuncSetAttribute(gemm_kernel,
                             cudaFuncAttributeMaxDynamicSharedMemorySize, SMEM_B);
        cudaFuncSetAttribute(im2col_kernel,
                             cudaFuncAttributeMaxDynamicSharedMemorySize, IMSMEM);
        attr_set = true;
    }

    pool_kernel<<<dim3(CIN, BB), 256>>>(x);
    att_kernel<<<1, 256>>>(w1, w2);
    wmix_kernel<<<dim3(COUT, BB), 256>>>(wc, we);
    im2col_kernel<<<dim3(HO, 2, BB), 256, IMSMEM>>>(x);
    gemm_kernel<<<dim3(8, BB), 256, SMEM_B>>>(cb, eb, out);
}